// round 16
// baseline (speedup 1.0000x reference)
#include <cuda_runtime.h>
#include <cuda_fp16.h>
#include <cstdint>

// LatticeCNN on GB300 — closed-form lattice conv decomposition + fp16 mma.sync.
// R15 base (149.6us) + launch-count reduction: transpose_h + prep(layer0) +
// prep(layer1) fused into one front kernel (8 launches total, layer-1 prep
// off the critical path). Per-layer weight-table buffers.
//
// join conv  == pointwise with 2-D prefix-summed weights
// meet conv  == pointwise(suffix weights) + x-prefix row strips + y-prefix col
//               strips + 2-D-prefix corner term

#define ALPHA  0.5f
#define SLOPE  0.01f
#define S      32
#define FOUT   128

__device__ __forceinline__ uint32_t pack_f16x2(float lo, float hi) {
    uint32_t r;
    asm("cvt.rn.f16x2.f32 %0, %1, %2;" : "=r"(r) : "f"(hi), "f"(lo));
    return r;
}
__device__ __forceinline__ uint32_t smem_u32(const void* p) {
    uint32_t a;
    asm("{ .reg .u64 t; cvta.to.shared.u64 t, %1; cvt.u32.u64 %0, t; }"
        : "=r"(a) : "l"(p));
    return a;
}
#define CP16(dst, src) \
    asm volatile("cp.async.cg.shared.global [%0], [%1], 16;" \
                 :: "r"(dst), "l"(src) : "memory")
#define CP_COMMIT() asm volatile("cp.async.commit_group;" ::: "memory")
#define CP_WAIT0()  asm volatile("cp.async.wait_group 0;" ::: "memory")

__device__ __forceinline__ void mma16(float (&d)[4], const uint4& a,
                                      uint32_t b0, uint32_t b1) {
    asm volatile(
        "mma.sync.aligned.m16n8k16.row.col.f32.f16.f16.f32 "
        "{%0,%1,%2,%3}, {%4,%5,%6,%7}, {%8,%9}, {%0,%1,%2,%3};"
        : "+f"(d[0]), "+f"(d[1]), "+f"(d[2]), "+f"(d[3])
        : "r"(a.x), "r"(a.y), "r"(a.z), "r"(a.w), "r"(b0), "r"(b1));
}

// ---------------- device scratch (no allocation allowed) ----------------
__device__ __half d_Xt0h [1024 * 64 * 64];   // layer0 input, pixel-major fp16
__device__ __half d_Yth  [1024 * 64 * 128];  // layer0 out / layer1 in, fp16
__device__ float  d_Yt2  [1024 * 64 * 128];  // layer1 out (pixel-major, fp32)
__device__ __half d_WCT0 [225 * 64 * FOUT];  // layer0 pointwise weights
__device__ __half d_MRST0[64 * 64 * FOUT];
__device__ __half d_MCST0[64 * 64 * FOUT];
__device__ __half d_MWT0 [64 * 64 * FOUT];
__device__ __half d_WCT1 [225 * 128 * FOUT]; // layer1 pointwise weights
__device__ __half d_MRST1[64 * 128 * FOUT];
__device__ __half d_MCST1[64 * 128 * FOUT];
__device__ __half d_MWT1 [64 * 128 * FOUT];
__device__ float  d_G    [224 * 64 * FOUT];  // row strip tiles  G[a][y]
__device__ float  d_CG   [224 * 64 * FOUT];  // col strip tiles  CG[b][x]
__device__ float  d_H    [49  * 64 * FOUT];  // corner tiles     H[a][b]

// ---------------- prep body (coalesced fp16 [g][f] tables) ----------------
__device__ __forceinline__ void prep_body(
    const float* __restrict__ mw, const float* __restrict__ jw,
    __half* __restrict__ WCT, __half* __restrict__ MRST,
    __half* __restrict__ MCST, __half* __restrict__ MWT,
    int Fin, int idx, int part)
{
    int f = idx % Fin;
    int g = idx / Fin;
    int ss = Fin * FOUT;
    int src = f * FOUT + g;          // original [a][b][f][g]

    float m[8][8];
    #pragma unroll
    for (int a = 0; a < 8; a++)
        #pragma unroll
        for (int b = 0; b < 8; b++)
            m[a][b] = mw[(a * 8 + b) * ss + src];

    if (part == 0) {
        #pragma unroll
        for (int a = 0; a < 8; a++)
            #pragma unroll
            for (int b = 0; b < 8; b++)
                MWT[(a * 8 + b) * ss + idx] = __float2half_rn(m[a][b]);
        {   // MCS[p][b] = sum_{a>=p} mw[a][b]
            float col[8];
            #pragma unroll
            for (int b = 0; b < 8; b++) col[b] = 0.f;
            #pragma unroll
            for (int p = 7; p >= 0; p--)
                #pragma unroll
                for (int b = 0; b < 8; b++) {
                    col[b] += m[p][b];
                    MCST[(p * 8 + b) * ss + idx] = __float2half_rn(col[b]);
                }
        }
        #pragma unroll
        for (int a = 0; a < 8; a++) {    // MRS[a][q] = sum_{b>=q}
            #pragma unroll
            for (int q = 6; q >= 0; q--) m[a][q] += m[a][q + 1];
            #pragma unroll
            for (int q = 0; q < 8; q++)
                MRST[(a * 8 + q) * ss + idx] = __float2half_rn(m[a][q]);
        }
        return;
    }

    // parts 1..3: full 2-D suffix of m, 2-D prefix of j, write WCT slice
    #pragma unroll
    for (int a = 0; a < 8; a++)
        #pragma unroll
        for (int q = 6; q >= 0; q--) m[a][q] += m[a][q + 1];
    #pragma unroll
    for (int b = 0; b < 8; b++)
        #pragma unroll
        for (int a = 6; a >= 0; a--) m[a][b] += m[a + 1][b];

    float j[8][8];
    #pragma unroll
    for (int a = 0; a < 8; a++)
        #pragma unroll
        for (int b = 0; b < 8; b++)
            j[a][b] = jw[(a * 8 + b) * ss + src];
    #pragma unroll
    for (int a = 0; a < 8; a++)
        #pragma unroll
        for (int b = 1; b < 8; b++) j[a][b] += j[a][b - 1];
    #pragma unroll
    for (int b = 0; b < 8; b++)
        #pragma unroll
        for (int a = 1; a < 8; a++) j[a][b] += j[a - 1][b];

    int cx0 = (part - 1) * 5;
    for (int cx = cx0; cx < cx0 + 5; cx++) {
        int ax = cx < 8 ? 0 : cx - 7;
        int jx = cx < 8 ? cx : 7;
        for (int cy = 0; cy < 15; cy++) {
            int ay = cy < 8 ? 0 : cy - 7;
            int jy = cy < 8 ? cy : 7;
            WCT[(cx * 15 + cy) * ss + idx] =
                __float2half_rn((1.0f - ALPHA) * m[ax][ay] + ALPHA * j[jx][jy]);
        }
    }
}

// ---------------- fused front: input transpose + both layers' prep --------
// blocks [0,4096)        : x [4096][1024] fp32 -> Xt0h [1024][4096] fp16
// blocks [4096,4224)     : layer0 prep  (32 blocks x 4 parts)
// blocks [4224,4480)     : layer1 prep  (64 blocks x 4 parts)
__global__ void __launch_bounds__(256) front_k(
    const float* __restrict__ x,
    const float* __restrict__ mw0, const float* __restrict__ jw0,
    const float* __restrict__ mw1, const float* __restrict__ jw1,
    __half* __restrict__ Xt0h,
    __half* __restrict__ WCT0, __half* __restrict__ MRST0,
    __half* __restrict__ MCST0, __half* __restrict__ MWT0,
    __half* __restrict__ WCT1, __half* __restrict__ MRST1,
    __half* __restrict__ MCST1, __half* __restrict__ MWT1)
{
    int bid = blockIdx.x;
    if (bid < 4096) {
        __shared__ float tile[32][33];
        int c0 = (bid & 31) * 32;        // column block in [0,1024)
        int r0 = (bid >> 5) * 32;        // row block in [0,4096)
        int tx = threadIdx.x & 31, ty = threadIdx.x >> 5;
        #pragma unroll
        for (int i = 0; i < 4; i++)
            tile[ty + 8 * i][tx] =
                x[(size_t)(r0 + ty + 8 * i) * 1024 + c0 + tx];
        __syncthreads();
        int tid = threadIdx.x;
        int rp = tid & 15, cc = tid >> 4;
        #pragma unroll
        for (int pass = 0; pass < 2; pass++) {
            int c = cc + pass * 16;
            uint32_t v = pack_f16x2(tile[2 * rp][c], tile[2 * rp + 1][c]);
            *(uint32_t*)(Xt0h + (size_t)(c0 + c) * 4096 + r0 + 2 * rp) = v;
        }
        return;
    }
    int b = bid - 4096;
    if (b < 128) {          // layer 0: Fin = 64
        int idx = (b & 31) * 256 + threadIdx.x;
        prep_body(mw0, jw0, WCT0, MRST0, MCST0, MWT0, 64, idx, b >> 5);
    } else {                // layer 1: Fin = 128
        int b2 = b - 128;
        int idx = (b2 & 63) * 256 + threadIdx.x;
        prep_body(mw1, jw1, WCT1, MRST1, MCST1, MWT1, 128, idx, b2 >> 6);
    }
}

// ---------------- final transpose: out [8192][1024] = Yt2 [1024][8192]^T ----
__global__ void transpose_k(float* __restrict__ dst, const float* __restrict__ src,
                            int R, int C)
{
    __shared__ float tile[32][33];
    int c0 = blockIdx.x * 32, r0 = blockIdx.y * 32;
    #pragma unroll
    for (int i = 0; i < 4; i++)
        tile[threadIdx.y + 8 * i][threadIdx.x] =
            src[(size_t)(r0 + threadIdx.y + 8 * i) * C + c0 + threadIdx.x];
    __syncthreads();
    #pragma unroll
    for (int i = 0; i < 4; i++)
        dst[(size_t)(c0 + threadIdx.y + 8 * i) * R + r0 + threadIdx.x] =
            tile[threadIdx.x][threadIdx.y + 8 * i];
}

// ---------------- GEMM unit: [64 x FIN] * W^T[128 x FIN] -> acc regs -------
// 8 warps: warp (wm,wn) = (wid/4, wid%4) owns rows [wm*32,+32) x cols [wn*32,+32).
// smem: raw fp16 tiles, halfword stride LDh = FIN+8 (LDh/2 == 4 mod 32 ->
// every f16x2 fragment gather is a conflict-free LDS.32). cp.async staging.
template <int FIN>
__device__ __forceinline__ void unit_gemm(const __half* __restrict__ X,
                                          const __half* __restrict__ W,
                                          __half* sm, float (&acc)[2][4][4])
{
    constexpr int LDh = FIN + 8;
    constexpr int CR  = FIN / 8;     // 16B chunks per row
    __half* Xs = sm;                 // [64][LDh]
    __half* Ws = sm + 64 * LDh;      // [128][LDh]
    const int tid = threadIdx.x;
    const uint32_t xs_base = smem_u32(Xs);
    const uint32_t ws_base = smem_u32(Ws);

    #pragma unroll
    for (int c = tid; c < 64 * CR; c += 256) {
        int r = c / CR, k = (c % CR) * 8;
        CP16(xs_base + (r * LDh + k) * 2, X + r * FIN + k);
    }
    #pragma unroll
    for (int c = tid; c < 128 * CR; c += 256) {
        int r = c / CR, k = (c % CR) * 8;
        CP16(ws_base + (r * LDh + k) * 2, W + r * FIN + k);
    }
    CP_COMMIT();
    CP_WAIT0();
    __syncthreads();

    const int lane = tid & 31, wid = tid >> 5;
    const int wm = wid >> 2, wn = wid & 3;
    const __half* Ax = Xs + (wm * 32 + (lane >> 2)) * LDh + (lane & 3) * 2;
    const __half* Bx = Ws + (wn * 32 + (lane >> 2)) * LDh + (lane & 3) * 2;

    #pragma unroll
    for (int kt = 0; kt < FIN / 16; kt++) {
        const int k0 = kt * 16;
        uint4 a0, a1;
        a0.x = *(const uint32_t*)(Ax + k0);
        a0.y = *(const uint32_t*)(Ax + 8 * LDh + k0);
        a0.z = *(const uint32_t*)(Ax + k0 + 8);
        a0.w = *(const uint32_t*)(Ax + 8 * LDh + k0 + 8);
        a1.x = *(const uint32_t*)(Ax + 16 * LDh + k0);
        a1.y = *(const uint32_t*)(Ax + 24 * LDh + k0);
        a1.z = *(const uint32_t*)(Ax + 16 * LDh + k0 + 8);
        a1.w = *(const uint32_t*)(Ax + 24 * LDh + k0 + 8);
        uint32_t b[4][2];
        #pragma unroll
        for (int nt = 0; nt < 4; nt++) {
            b[nt][0] = *(const uint32_t*)(Bx + nt * 8 * LDh + k0);
            b[nt][1] = *(const uint32_t*)(Bx + nt * 8 * LDh + k0 + 8);
        }
        #pragma unroll
        for (int nt = 0; nt < 4; nt++) {
            mma16(acc[0][nt], a0, b[nt][0], b[nt][1]);
            mma16(acc[1][nt], a1, b[nt][0], b[nt][1]);
        }
    }
}

// ---------------- strips/corner: 497 units, 1 per block ----------------
template <int FIN>
__global__ void __launch_bounds__(256) strips_mc(
    const __half* __restrict__ Xt, const __half* __restrict__ MRST,
    const __half* __restrict__ MCST, const __half* __restrict__ MWT,
    float* __restrict__ G, float* __restrict__ CG, float* __restrict__ H)
{
    extern __shared__ __half smh[];
    int u = blockIdx.x;
    size_t ss = (size_t)FIN * FOUT;
    const __half* X; const __half* W; float* dst;
    if (u < 224) {
        int a = u >> 5, Y = u & 31;
        int q = Y > 24 ? Y - 24 : 0;
        X = Xt + (size_t)((a + 24) * S + Y) * 64 * FIN;
        W = MRST + (size_t)(a * 8 + q) * ss;
        dst = G + (size_t)u * 64 * FOUT;
    } else if (u < 448) {
        int t = u - 224;
        int b = t >> 5, Xc = t & 31;
        int p = Xc > 24 ? Xc - 24 : 0;
        X = Xt + (size_t)(Xc * S + b + 24) * 64 * FIN;
        W = MCST + (size_t)(p * 8 + b) * ss;
        dst = CG + (size_t)t * 64 * FOUT;
    } else {
        int t = u - 448;
        int a = t / 7, b = t % 7;
        X = Xt + (size_t)((a + 24) * S + b + 24) * 64 * FIN;
        W = MWT + (size_t)(a * 8 + b) * ss;
        dst = H + (size_t)t * 64 * FOUT;
    }

    float acc[2][4][4] = {};
    unit_gemm<FIN>(X, W, smh, acc);

    int lane = threadIdx.x & 31, wid = threadIdx.x >> 5;
    int wm = wid >> 2, wn = wid & 3;
    int r0 = wm * 32 + (lane >> 2);
    #pragma unroll
    for (int mt = 0; mt < 2; mt++)
        #pragma unroll
        for (int nt = 0; nt < 4; nt++) {
            int g = wn * 32 + nt * 8 + (lane & 3) * 2;
            int r = r0 + mt * 16;
            *(float2*)(dst + r * FOUT + g)       = make_float2(acc[mt][nt][0], acc[mt][nt][1]);
            *(float2*)(dst + (r + 8) * FOUT + g) = make_float2(acc[mt][nt][2], acc[mt][nt][3]);
        }
}

// ---------------- merged prefix pass: rows(G) + rows(CG) + 2-D(H) ----------
__global__ void prefix_all_k(float* __restrict__ G, float* __restrict__ CG,
                             float* __restrict__ H)
{
    int bid = blockIdx.x;
    if (bid < 2048) {
        int t = bid * 256 + threadIdx.x;
        float* buf = (t < 32 * 8192) ? G : CG;
        int tt = t & (32 * 8192 - 1);
        int yy = tt >> 13, mg = tt & 8191;
        float run = 0.f;
        #pragma unroll
        for (int a = 0; a < 7; a++) {
            int idx = (a * 32 + yy) * 8192 + mg;
            run += buf[idx];
            buf[idx] = run;
        }
    } else {
        int mg = (bid - 2048) * 256 + threadIdx.x;
        float colA[7];
        #pragma unroll
        for (int b = 0; b < 7; b++) colA[b] = 0.f;
        #pragma unroll
        for (int a = 0; a < 7; a++) {
            float run = 0.f;
            #pragma unroll
            for (int b = 0; b < 7; b++) {
                int idx = (a * 7 + b) * 8192 + mg;
                run += H[idx];
                colA[b] += run;
                H[idx] = colA[b];
            }
        }
    }
}

// ---------------- combine: 1024 pixels, 1 per block ----------------
template <int FIN, bool OUT_HALF>
__global__ void __launch_bounds__(256) combine_mc(
    const __half* __restrict__ Xt, const __half* __restrict__ WCT,
    const float* __restrict__ Gc, const float* __restrict__ CGc,
    const float* __restrict__ Hc, const float* __restrict__ mb,
    const float* __restrict__ jb, void* __restrict__ Yout)
{
    extern __shared__ __half smh[];
    int p = blockIdx.x;
    int X = p >> 5, Y = p & 31;
    int cx = X <= 24 ? (X < 7 ? X : 7) : X - 17;
    int cy = Y <= 24 ? (Y < 7 ? Y : 7) : Y - 17;
    size_t ss = (size_t)FIN * FOUT;

    float acc[2][4][4] = {};
    unit_gemm<FIN>(Xt + (size_t)p * 64 * FIN,
                   WCT + (size_t)(cx * 15 + cy) * ss, smh, acc);

    const float ms = 1.0f - ALPHA;
    const float* Gp = (X >= 25) ? Gc + (size_t)((X - 25) * S + Y) * 64 * FOUT : 0;
    const float* Cp = (Y >= 25) ? CGc + (size_t)((Y - 25) * S + X) * 64 * FOUT : 0;
    const float* Hp = (X >= 25 && Y >= 25)
        ? Hc + (size_t)((X - 25) * 7 + (Y - 25)) * 64 * FOUT : 0;

    int lane = threadIdx.x & 31, wid = threadIdx.x >> 5;
    int wm = wid >> 2, wn = wid & 3;
    int r0 = wm * 32 + (lane >> 2);

    #pragma unroll
    for (int nt = 0; nt < 4; nt++) {
        int g = wn * 32 + nt * 8 + (lane & 3) * 2;
        float2 bias = make_float2(ms * mb[g]     + ALPHA * jb[g],
                                  ms * mb[g + 1] + ALPHA * jb[g + 1]);
        #pragma unroll
        for (int mt = 0; mt < 2; mt++) {
            #pragma unroll
            for (int half = 0; half < 2; half++) {
                int r = r0 + mt * 16 + half * 8;
                float v0 = acc[mt][nt][half * 2], v1 = acc[mt][nt][half * 2 + 1];
                if (Gp) {
                    float2 s2 = *(const float2*)(Gp + r * FOUT + g);
                    v0 += ms * s2.x; v1 += ms * s2.y;
                }
                if (Cp) {
                    float2 s2 = *(const float2*)(Cp + r * FOUT + g);
                    v0 += ms * s2.x; v1 += ms * s2.y;
                }
                if (Hp) {
                    float2 s2 = *(const float2*)(Hp + r * FOUT + g);
                    v0 += ms * s2.x; v1 += ms * s2.y;
                }
                v0 += bias.x; v1 += bias.y;
                v0 = fmaxf(v0, SLOPE * v0);
                v1 = fmaxf(v1, SLOPE * v1);
                if (OUT_HALF) {
                    __half* O = (__half*)Yout + (size_t)p * 64 * FOUT;
                    *(uint32_t*)(O + r * FOUT + g) = pack_f16x2(v0, v1);
                } else {
                    float* O = (float*)Yout + (size_t)p * 64 * FOUT;
                    *(float2*)(O + r * FOUT + g) = make_float2(v0, v1);
                }
            }
        }
    }
}

// ---------------- host launch ----------------
extern "C" void kernel_launch(void* const* d_in, const int* in_sizes, int n_in,
                              void* d_out, int out_size)
{
    const float* x   = (const float*)d_in[0];
    const float* mw0 = (const float*)d_in[5];
    const float* mb0 = (const float*)d_in[6];
    const float* jw0 = (const float*)d_in[7];
    const float* jb0 = (const float*)d_in[8];
    const float* mw1 = (const float*)d_in[9];
    const float* mb1 = (const float*)d_in[10];
    const float* jw1 = (const float*)d_in[11];
    const float* jb1 = (const float*)d_in[12];
    float* out = (float*)d_out;

    __half *Xt0h, *Yth, *WCT0, *MRST0, *MCST0, *MWT0, *WCT1, *MRST1, *MCST1, *MWT1;
    float *Yt2, *G, *CG, *H;
    cudaGetSymbolAddress((void**)&Xt0h,  d_Xt0h);
    cudaGetSymbolAddress((void**)&Yth,   d_Yth);
    cudaGetSymbolAddress((void**)&Yt2,   d_Yt2);
    cudaGetSymbolAddress((void**)&WCT0,  d_WCT0);
    cudaGetSymbolAddress((void**)&MRST0, d_MRST0);
    cudaGetSymbolAddress((void**)&MCST0, d_MCST0);
    cudaGetSymbolAddress((void**)&MWT0,  d_MWT0);
    cudaGetSymbolAddress((void**)&WCT1,  d_WCT1);
    cudaGetSymbolAddress((void**)&MRST1, d_MRST1);
    cudaGetSymbolAddress((void**)&MCST1, d_MCST1);
    cudaGetSymbolAddress((void**)&MWT1,  d_MWT1);
    cudaGetSymbolAddress((void**)&G,     d_G);
    cudaGetSymbolAddress((void**)&CG,    d_CG);
    cudaGetSymbolAddress((void**)&H,     d_H);

    const int smem64  = 192 * (64 + 8)  * 2;   // 27648 B
    const int smem128 = 192 * (128 + 8) * 2;   // 52224 B
    cudaFuncSetAttribute(strips_mc<64>,  cudaFuncAttributeMaxDynamicSharedMemorySize, smem64);
    cudaFuncSetAttribute(combine_mc<64, true>,
                         cudaFuncAttributeMaxDynamicSharedMemorySize, smem64);
    cudaFuncSetAttribute(strips_mc<128>, cudaFuncAttributeMaxDynamicSharedMemorySize, smem128);
    cudaFuncSetAttribute(combine_mc<128, false>,
                         cudaFuncAttributeMaxDynamicSharedMemorySize, smem128);

    // 1) fused front: input transpose + both layers' prep (4480 blocks)
    front_k<<<4480, 256>>>(x, mw0, jw0, mw1, jw1, Xt0h,
                           WCT0, MRST0, MCST0, MWT0,
                           WCT1, MRST1, MCST1, MWT1);

    // ---- layer 0: Fin = 64 ----
    strips_mc<64><<<497, 256, smem64>>>(Xt0h, MRST0, MCST0, MWT0, G, CG, H);
    prefix_all_k<<<2080, 256>>>(G, CG, H);
    combine_mc<64, true><<<1024, 256, smem64>>>(Xt0h, WCT0, G, CG, H, mb0, jb0, Yth);

    // ---- layer 1: Fin = 128 ----
    strips_mc<128><<<497, 256, smem128>>>(Yth, MRST1, MCST1, MWT1, G, CG, H);
    prefix_all_k<<<2080, 256>>>(G, CG, H);
    combine_mc<128, false><<<1024, 256, smem128>>>(Yth, WCT1, G, CG, H, mb1, jb1, Yt2);

    // 8) Yt2 [1024][8192] -> out [8192][1024]
    dim3 tb(32, 8);
    transpose_k<<<dim3(8192 / 32, 1024 / 32), tb>>>(out, Yt2, 1024, 8192);
}

// round 17
// speedup vs baseline: 1.0852x; 1.0852x over previous
#include <cuda_runtime.h>
#include <cuda_fp16.h>
#include <cstdint>

// LatticeCNN on GB300 — closed-form lattice conv decomposition + fp16 mma.sync.
// R15 base (149.6us: coalesced prep, fp16-resident data, cp.async staging)
// + fp16 G/CG/H strip buffers (halves prefix-pass and strip-add traffic).
//
// join conv  == pointwise with 2-D prefix-summed weights
// meet conv  == pointwise(suffix weights) + x-prefix row strips + y-prefix col
//               strips + 2-D-prefix corner term

#define ALPHA  0.5f
#define SLOPE  0.01f
#define S      32
#define FOUT   128

__device__ __forceinline__ uint32_t pack_f16x2(float lo, float hi) {
    uint32_t r;
    asm("cvt.rn.f16x2.f32 %0, %1, %2;" : "=r"(r) : "f"(hi), "f"(lo));
    return r;
}
__device__ __forceinline__ uint32_t smem_u32(const void* p) {
    uint32_t a;
    asm("{ .reg .u64 t; cvta.to.shared.u64 t, %1; cvt.u32.u64 %0, t; }"
        : "=r"(a) : "l"(p));
    return a;
}
#define CP16(dst, src) \
    asm volatile("cp.async.cg.shared.global [%0], [%1], 16;" \
                 :: "r"(dst), "l"(src) : "memory")
#define CP_COMMIT() asm volatile("cp.async.commit_group;" ::: "memory")
#define CP_WAIT0()  asm volatile("cp.async.wait_group 0;" ::: "memory")

__device__ __forceinline__ void mma16(float (&d)[4], const uint4& a,
                                      uint32_t b0, uint32_t b1) {
    asm volatile(
        "mma.sync.aligned.m16n8k16.row.col.f32.f16.f16.f32 "
        "{%0,%1,%2,%3}, {%4,%5,%6,%7}, {%8,%9}, {%0,%1,%2,%3};"
        : "+f"(d[0]), "+f"(d[1]), "+f"(d[2]), "+f"(d[3])
        : "r"(a.x), "r"(a.y), "r"(a.z), "r"(a.w), "r"(b0), "r"(b1));
}

// ---------------- device scratch (no allocation allowed) ----------------
__device__ __half d_Xt0h[1024 * 64 * 64];    // layer0 input, pixel-major fp16
__device__ __half d_Yth [1024 * 64 * 128];   // layer0 out / layer1 in, fp16
__device__ float  d_Yt2 [1024 * 64 * 128];   // layer1 out (pixel-major, fp32)
__device__ __half d_WCT [225 * 128 * FOUT];  // pointwise weights [class][g][f]
__device__ __half d_MRST[64 * 128 * FOUT];   // row-suffix  [a*8+q][g][f]
__device__ __half d_MCST[64 * 128 * FOUT];   // col-suffix  [p*8+b][g][f]
__device__ __half d_MWT [64 * 128 * FOUT];   // raw meet    [a*8+b][g][f]
__device__ __half d_G   [224 * 64 * FOUT];   // row strip tiles  G[a][y] (fp16)
__device__ __half d_CG  [224 * 64 * FOUT];   // col strip tiles  CG[b][x] (fp16)
__device__ __half d_H   [49  * 64 * FOUT];   // corner tiles     H[a][b] (fp16)

// ---------------- transposes ----------------
__global__ void transpose_h_k(__half* __restrict__ dst, const float* __restrict__ src,
                              int R, int C)
{
    __shared__ float tile[32][33];
    int c0 = blockIdx.x * 32, r0 = blockIdx.y * 32;
    #pragma unroll
    for (int i = 0; i < 4; i++)
        tile[threadIdx.y + 8 * i][threadIdx.x] =
            src[(size_t)(r0 + threadIdx.y + 8 * i) * C + c0 + threadIdx.x];
    __syncthreads();
    int tid = threadIdx.y * 32 + threadIdx.x;
    int rp = tid & 15, cc = tid >> 4;
    #pragma unroll
    for (int pass = 0; pass < 2; pass++) {
        int c = cc + pass * 16;
        uint32_t v = pack_f16x2(tile[2 * rp][c], tile[2 * rp + 1][c]);
        *(uint32_t*)(dst + (size_t)(c0 + c) * R + r0 + 2 * rp) = v;
    }
}

__global__ void transpose_k(float* __restrict__ dst, const float* __restrict__ src,
                            int R, int C)
{
    __shared__ float tile[32][33];
    int c0 = blockIdx.x * 32, r0 = blockIdx.y * 32;
    #pragma unroll
    for (int i = 0; i < 4; i++)
        tile[threadIdx.y + 8 * i][threadIdx.x] =
            src[(size_t)(r0 + threadIdx.y + 8 * i) * C + c0 + threadIdx.x];
    __syncthreads();
    #pragma unroll
    for (int i = 0; i < 4; i++)
        dst[(size_t)(c0 + threadIdx.y + 8 * i) * R + r0 + threadIdx.x] =
            tile[threadIdx.x][threadIdx.y + 8 * i];
}

// ---------------- per-layer weight-table prep (coalesced fp16 writes) ------
__global__ void prep_k(const float* __restrict__ mw, const float* __restrict__ jw,
                       __half* __restrict__ WCT, __half* __restrict__ MRST,
                       __half* __restrict__ MCST, __half* __restrict__ MWT, int Fin)
{
    int idx = blockIdx.x * blockDim.x + threadIdx.x;
    if (idx >= Fin * FOUT) return;
    int f = idx % Fin, g = idx / Fin;
    int ss = Fin * FOUT;
    int src = f * FOUT + g;
    int part = blockIdx.y;

    float m[8][8];
    #pragma unroll
    for (int a = 0; a < 8; a++)
        #pragma unroll
        for (int b = 0; b < 8; b++)
            m[a][b] = mw[(a * 8 + b) * ss + src];

    if (part == 0) {
        #pragma unroll
        for (int a = 0; a < 8; a++)
            #pragma unroll
            for (int b = 0; b < 8; b++)
                MWT[(a * 8 + b) * ss + idx] = __float2half_rn(m[a][b]);
        {
            float col[8];
            #pragma unroll
            for (int b = 0; b < 8; b++) col[b] = 0.f;
            #pragma unroll
            for (int p = 7; p >= 0; p--)
                #pragma unroll
                for (int b = 0; b < 8; b++) {
                    col[b] += m[p][b];
                    MCST[(p * 8 + b) * ss + idx] = __float2half_rn(col[b]);
                }
        }
        #pragma unroll
        for (int a = 0; a < 8; a++) {
            #pragma unroll
            for (int q = 6; q >= 0; q--) m[a][q] += m[a][q + 1];
            #pragma unroll
            for (int q = 0; q < 8; q++)
                MRST[(a * 8 + q) * ss + idx] = __float2half_rn(m[a][q]);
        }
        return;
    }

    #pragma unroll
    for (int a = 0; a < 8; a++)
        #pragma unroll
        for (int q = 6; q >= 0; q--) m[a][q] += m[a][q + 1];
    #pragma unroll
    for (int b = 0; b < 8; b++)
        #pragma unroll
        for (int a = 6; a >= 0; a--) m[a][b] += m[a + 1][b];

    float j[8][8];
    #pragma unroll
    for (int a = 0; a < 8; a++)
        #pragma unroll
        for (int b = 0; b < 8; b++)
            j[a][b] = jw[(a * 8 + b) * ss + src];
    #pragma unroll
    for (int a = 0; a < 8; a++)
        #pragma unroll
        for (int b = 1; b < 8; b++) j[a][b] += j[a][b - 1];
    #pragma unroll
    for (int b = 0; b < 8; b++)
        #pragma unroll
        for (int a = 1; a < 8; a++) j[a][b] += j[a - 1][b];

    int cx0 = (part - 1) * 5;
    for (int cx = cx0; cx < cx0 + 5; cx++) {
        int ax = cx < 8 ? 0 : cx - 7;
        int jx = cx < 8 ? cx : 7;
        for (int cy = 0; cy < 15; cy++) {
            int ay = cy < 8 ? 0 : cy - 7;
            int jy = cy < 8 ? cy : 7;
            WCT[(cx * 15 + cy) * ss + idx] =
                __float2half_rn((1.0f - ALPHA) * m[ax][ay] + ALPHA * j[jx][jy]);
        }
    }
}

// ---------------- GEMM unit: [64 x FIN] * W^T[128 x FIN] -> acc regs -------
template <int FIN>
__device__ __forceinline__ void unit_gemm(const __half* __restrict__ X,
                                          const __half* __restrict__ W,
                                          __half* sm, float (&acc)[2][4][4])
{
    constexpr int LDh = FIN + 8;
    constexpr int CR  = FIN / 8;
    __half* Xs = sm;
    __half* Ws = sm + 64 * LDh;
    const int tid = threadIdx.x;
    const uint32_t xs_base = smem_u32(Xs);
    const uint32_t ws_base = smem_u32(Ws);

    #pragma unroll
    for (int c = tid; c < 64 * CR; c += 256) {
        int r = c / CR, k = (c % CR) * 8;
        CP16(xs_base + (r * LDh + k) * 2, X + r * FIN + k);
    }
    #pragma unroll
    for (int c = tid; c < 128 * CR; c += 256) {
        int r = c / CR, k = (c % CR) * 8;
        CP16(ws_base + (r * LDh + k) * 2, W + r * FIN + k);
    }
    CP_COMMIT();
    CP_WAIT0();
    __syncthreads();

    const int lane = tid & 31, wid = tid >> 5;
    const int wm = wid >> 2, wn = wid & 3;
    const __half* Ax = Xs + (wm * 32 + (lane >> 2)) * LDh + (lane & 3) * 2;
    const __half* Bx = Ws + (wn * 32 + (lane >> 2)) * LDh + (lane & 3) * 2;

    #pragma unroll
    for (int kt = 0; kt < FIN / 16; kt++) {
        const int k0 = kt * 16;
        uint4 a0, a1;
        a0.x = *(const uint32_t*)(Ax + k0);
        a0.y = *(const uint32_t*)(Ax + 8 * LDh + k0);
        a0.z = *(const uint32_t*)(Ax + k0 + 8);
        a0.w = *(const uint32_t*)(Ax + 8 * LDh + k0 + 8);
        a1.x = *(const uint32_t*)(Ax + 16 * LDh + k0);
        a1.y = *(const uint32_t*)(Ax + 24 * LDh + k0);
        a1.z = *(const uint32_t*)(Ax + 16 * LDh + k0 + 8);
        a1.w = *(const uint32_t*)(Ax + 24 * LDh + k0 + 8);
        uint32_t b[4][2];
        #pragma unroll
        for (int nt = 0; nt < 4; nt++) {
            b[nt][0] = *(const uint32_t*)(Bx + nt * 8 * LDh + k0);
            b[nt][1] = *(const uint32_t*)(Bx + nt * 8 * LDh + k0 + 8);
        }
        #pragma unroll
        for (int nt = 0; nt < 4; nt++) {
            mma16(acc[0][nt], a0, b[nt][0], b[nt][1]);
            mma16(acc[1][nt], a1, b[nt][0], b[nt][1]);
        }
    }
}

// ---------------- strips/corner: 497 units, 1 per block (fp16 out) ---------
template <int FIN>
__global__ void __launch_bounds__(256) strips_mc(
    const __half* __restrict__ Xt, const __half* __restrict__ MRST,
    const __half* __restrict__ MCST, const __half* __restrict__ MWT,
    __half* __restrict__ G, __half* __restrict__ CG, __half* __restrict__ H)
{
    extern __shared__ __half smh[];
    int u = blockIdx.x;
    size_t ss = (size_t)FIN * FOUT;
    const __half* X; const __half* W; __half* dst;
    if (u < 224) {
        int a = u >> 5, Y = u & 31;
        int q = Y > 24 ? Y - 24 : 0;
        X = Xt + (size_t)((a + 24) * S + Y) * 64 * FIN;
        W = MRST + (size_t)(a * 8 + q) * ss;
        dst = G + (size_t)u * 64 * FOUT;
    } else if (u < 448) {
        int t = u - 224;
        int b = t >> 5, Xc = t & 31;
        int p = Xc > 24 ? Xc - 24 : 0;
        X = Xt + (size_t)(Xc * S + b + 24) * 64 * FIN;
        W = MCST + (size_t)(p * 8 + b) * ss;
        dst = CG + (size_t)t * 64 * FOUT;
    } else {
        int t = u - 448;
        int a = t / 7, b = t % 7;
        X = Xt + (size_t)((a + 24) * S + b + 24) * 64 * FIN;
        W = MWT + (size_t)(a * 8 + b) * ss;
        dst = H + (size_t)t * 64 * FOUT;
    }

    float acc[2][4][4] = {};
    unit_gemm<FIN>(X, W, smh, acc);

    int lane = threadIdx.x & 31, wid = threadIdx.x >> 5;
    int wm = wid >> 2, wn = wid & 3;
    int r0 = wm * 32 + (lane >> 2);
    #pragma unroll
    for (int mt = 0; mt < 2; mt++)
        #pragma unroll
        for (int nt = 0; nt < 4; nt++) {
            int g = wn * 32 + nt * 8 + (lane & 3) * 2;
            int r = r0 + mt * 16;
            *(uint32_t*)(dst + r * FOUT + g)       = pack_f16x2(acc[mt][nt][0], acc[mt][nt][1]);
            *(uint32_t*)(dst + (r + 8) * FOUT + g) = pack_f16x2(acc[mt][nt][2], acc[mt][nt][3]);
        }
}

// ---------------- merged prefix pass (fp16 buffers, fp32 accumulation) -----
// rows part: 2 buffers x 32 yy x 4096 half2-units -> 1024 blocks
// H part:    49 tiles x 4096 half2-units          -> 16 blocks
__global__ void prefix_all_k(__half* __restrict__ G, __half* __restrict__ CG,
                             __half* __restrict__ H)
{
    int bid = blockIdx.x;
    if (bid < 1024) {
        int t = bid * 256 + threadIdx.x;           // over 2 * 32 * 4096
        __half* buf = (t < 32 * 4096) ? G : CG;
        int tt = t & (32 * 4096 - 1);
        int yy = tt >> 12, mg = tt & 4095;         // half2 units
        float rx = 0.f, ry = 0.f;
        #pragma unroll
        for (int a = 0; a < 7; a++) {
            uint32_t* p = (uint32_t*)buf + (a * 32 + yy) * 4096 + mg;
            __half2 h = *(__half2*)p;
            rx += __low2float(h); ry += __high2float(h);
            *p = pack_f16x2(rx, ry);
        }
    } else {
        int mg = (bid - 1024) * 256 + threadIdx.x; // 0..4095
        float cAx[7], cAy[7];
        #pragma unroll
        for (int b = 0; b < 7; b++) { cAx[b] = 0.f; cAy[b] = 0.f; }
        #pragma unroll
        for (int a = 0; a < 7; a++) {
            float rx = 0.f, ry = 0.f;
            #pragma unroll
            for (int b = 0; b < 7; b++) {
                uint32_t* p = (uint32_t*)H + (a * 7 + b) * 4096 + mg;
                __half2 h = *(__half2*)p;
                rx += __low2float(h); ry += __high2float(h);
                cAx[b] += rx; cAy[b] += ry;
                *p = pack_f16x2(cAx[b], cAy[b]);
            }
        }
    }
}

// ---------------- combine: 1024 pixels, 1 per block ----------------
template <int FIN, bool OUT_HALF>
__global__ void __launch_bounds__(256) combine_mc(
    const __half* __restrict__ Xt, const __half* __restrict__ WCT,
    const __half* __restrict__ Gc, const __half* __restrict__ CGc,
    const __half* __restrict__ Hc, const float* __restrict__ mb,
    const float* __restrict__ jb, void* __restrict__ Yout)
{
    extern __shared__ __half smh[];
    int p = blockIdx.x;
    int X = p >> 5, Y = p & 31;
    int cx = X <= 24 ? (X < 7 ? X : 7) : X - 17;
    int cy = Y <= 24 ? (Y < 7 ? Y : 7) : Y - 17;
    size_t ss = (size_t)FIN * FOUT;

    float acc[2][4][4] = {};
    unit_gemm<FIN>(Xt + (size_t)p * 64 * FIN,
                   WCT + (size_t)(cx * 15 + cy) * ss, smh, acc);

    const float ms = 1.0f - ALPHA;
    const __half* Gp = (X >= 25) ? Gc + (size_t)((X - 25) * S + Y) * 64 * FOUT : 0;
    const __half* Cp = (Y >= 25) ? CGc + (size_t)((Y - 25) * S + X) * 64 * FOUT : 0;
    const __half* Hp = (X >= 25 && Y >= 25)
        ? Hc + (size_t)((X - 25) * 7 + (Y - 25)) * 64 * FOUT : 0;

    int lane = threadIdx.x & 31, wid = threadIdx.x >> 5;
    int wm = wid >> 2, wn = wid & 3;
    int r0 = wm * 32 + (lane >> 2);

    #pragma unroll
    for (int nt = 0; nt < 4; nt++) {
        int g = wn * 32 + nt * 8 + (lane & 3) * 2;
        float2 bias = make_float2(ms * mb[g]     + ALPHA * jb[g],
                                  ms * mb[g + 1] + ALPHA * jb[g + 1]);
        #pragma unroll
        for (int mt = 0; mt < 2; mt++) {
            #pragma unroll
            for (int half = 0; half < 2; half++) {
                int r = r0 + mt * 16 + half * 8;
                float v0 = acc[mt][nt][half * 2], v1 = acc[mt][nt][half * 2 + 1];
                if (Gp) {
                    __half2 h = *(const __half2*)(Gp + r * FOUT + g);
                    v0 += ms * __low2float(h); v1 += ms * __high2float(h);
                }
                if (Cp) {
                    __half2 h = *(const __half2*)(Cp + r * FOUT + g);
                    v0 += ms * __low2float(h); v1 += ms * __high2float(h);
                }
                if (Hp) {
                    __half2 h = *(const __half2*)(Hp + r * FOUT + g);
                    v0 += ms * __low2float(h); v1 += ms * __high2float(h);
                }
                v0 += bias.x; v1 += bias.y;
                v0 = fmaxf(v0, SLOPE * v0);
                v1 = fmaxf(v1, SLOPE * v1);
                if (OUT_HALF) {
                    __half* O = (__half*)Yout + (size_t)p * 64 * FOUT;
                    *(uint32_t*)(O + r * FOUT + g) = pack_f16x2(v0, v1);
                } else {
                    float* O = (float*)Yout + (size_t)p * 64 * FOUT;
                    *(float2*)(O + r * FOUT + g) = make_float2(v0, v1);
                }
            }
        }
    }
}

// ---------------- host launch ----------------
extern "C" void kernel_launch(void* const* d_in, const int* in_sizes, int n_in,
                              void* d_out, int out_size)
{
    const float* x   = (const float*)d_in[0];
    const float* mw0 = (const float*)d_in[5];
    const float* mb0 = (const float*)d_in[6];
    const float* jw0 = (const float*)d_in[7];
    const float* jb0 = (const float*)d_in[8];
    const float* mw1 = (const float*)d_in[9];
    const float* mb1 = (const float*)d_in[10];
    const float* jw1 = (const float*)d_in[11];
    const float* jb1 = (const float*)d_in[12];
    float* out = (float*)d_out;

    __half *Xt0h, *Yth, *WCT, *MRST, *MCST, *MWT, *G, *CG, *H;
    float *Yt2;
    cudaGetSymbolAddress((void**)&Xt0h, d_Xt0h);
    cudaGetSymbolAddress((void**)&Yth,  d_Yth);
    cudaGetSymbolAddress((void**)&Yt2,  d_Yt2);
    cudaGetSymbolAddress((void**)&WCT,  d_WCT);
    cudaGetSymbolAddress((void**)&MRST, d_MRST);
    cudaGetSymbolAddress((void**)&MCST, d_MCST);
    cudaGetSymbolAddress((void**)&MWT,  d_MWT);
    cudaGetSymbolAddress((void**)&G,    d_G);
    cudaGetSymbolAddress((void**)&CG,   d_CG);
    cudaGetSymbolAddress((void**)&H,    d_H);

    const int smem64  = 192 * (64 + 8)  * 2;   // 27648 B
    const int smem128 = 192 * (128 + 8) * 2;   // 52224 B
    cudaFuncSetAttribute(strips_mc<64>,  cudaFuncAttributeMaxDynamicSharedMemorySize, smem64);
    cudaFuncSetAttribute(combine_mc<64, true>,
                         cudaFuncAttributeMaxDynamicSharedMemorySize, smem64);
    cudaFuncSetAttribute(strips_mc<128>, cudaFuncAttributeMaxDynamicSharedMemorySize, smem128);
    cudaFuncSetAttribute(combine_mc<128, false>,
                         cudaFuncAttributeMaxDynamicSharedMemorySize, smem128);

    dim3 tb(32, 8);
    // x [4096][1024] fp32 -> Xt0h [1024][4096] fp16
    transpose_h_k<<<dim3(1024 / 32, 4096 / 32), tb>>>(Xt0h, x, 4096, 1024);

    // ---- layer 0: Fin = 64 ----
    prep_k<<<dim3((64 * 128) / 256, 4), 256>>>(mw0, jw0, WCT, MRST, MCST, MWT, 64);
    strips_mc<64><<<497, 256, smem64>>>(Xt0h, MRST, MCST, MWT, G, CG, H);
    prefix_all_k<<<1040, 256>>>(G, CG, H);
    combine_mc<64, true><<<1024, 256, smem64>>>(Xt0h, WCT, G, CG, H, mb0, jb0, Yth);

    // ---- layer 1: Fin = 128 ----
    prep_k<<<dim3((128 * 128) / 256, 4), 256>>>(mw1, jw1, WCT, MRST, MCST, MWT, 128);
    strips_mc<128><<<497, 256, smem128>>>(Yth, MRST, MCST, MWT, G, CG, H);
    prefix_all_k<<<1040, 256>>>(G, CG, H);
    combine_mc<128, false><<<1024, 256, smem128>>>(Yth, WCT, G, CG, H, mb1, jb1, Yt2);

    // Yt2 [1024][8192] -> out [8192][1024]
    transpose_k<<<dim3(8192 / 32, 1024 / 32), tb>>>(out, Yt2, 1024, 8192);
}